// round 15
// baseline (speedup 1.0000x reference)
#include <cuda_runtime.h>

#define LOG2E 1.4426950408889634f
#define N_EN  20000
#define M_MEN 256

// Block: 256 threads = 8 warps. Warp = 4 entities x 8 chunk-slots.
//   lane = n_sub*8 + c  (n_sub in 0..3, c in 0..7)
// Thread: entity chunk (n, c) in registers; loops 32 mentions; mention chunk
// from padded smem (8 distinct addrs/warp, conflict-free); shfl-reduce over c.
// All 8 dims per chunk on the packed-poly path:
//   v = relu(y) + t*R(t),  t = 2^-|y|,  R(t) ~= log2(1+t)/t (deg-5 Horner,
//   f32x2 packed FFMA2 -> feeds all 128 FP32 cores from 1 issue slot).

typedef unsigned long long ull;

__device__ __forceinline__ float ex2f(float x){float r;asm("ex2.approx.ftz.f32 %0,%1;":"=f"(r):"f"(x));return r;}
__device__ __forceinline__ float lg2f(float x){float r;asm("lg2.approx.ftz.f32 %0,%1;":"=f"(r):"f"(x));return r;}

__device__ __forceinline__ ull pk(float a,float b){ull r;asm("mov.b64 %0,{%1,%2};":"=l"(r):"f"(a),"f"(b));return r;}
__device__ __forceinline__ void upk(ull v,float&a,float&b){asm("mov.b64 {%0,%1},%2;":"=f"(a),"=f"(b):"l"(v));}
__device__ __forceinline__ ull ffma2(ull a,ull b,ull c){ull r;asm("fma.rn.f32x2 %0,%1,%2,%3;":"=l"(r):"l"(a),"l"(b),"l"(c));return r;}
__device__ __forceinline__ ull fmul2(ull a,ull b){ull r;asm("mul.rn.f32x2 %0,%1,%2;":"=l"(r):"l"(a),"l"(b));return r;}

// R(t) = Q(t)/t where Q ~= log2(1+t) on [0,1] (deg-6 Chebyshev closed form,
// b0 dropped: its 3.84e-6 t-independent shift cancels exactly through Gm).
// R in [0.693, 1.443] > 0 on [0,1] -> v > 0, chunk products positive.
struct PolyC { ull b6,b5,b4,b3,b2,b1; };

// One 8-dim chunk: lg2( prod_d log2(1+2^{y_d}) ), y = min(mZ,eZ)-max(mz,ez).
// ml: 16 floats (lo[0..7], hi[8..15]); ez/eZ: entity registers.
__device__ __forceinline__ float chunk_lg2(const float* ml,
                                           const float* ez, const float* eZ,
                                           const PolyC& C){
    ull prod = 0;
#pragma unroll
    for (int p = 0; p < 4; ++p){
        float y0 = fminf(ml[8+2*p], eZ[2*p])   - fmaxf(ml[2*p],   ez[2*p]);
        float y1 = fminf(ml[9+2*p], eZ[2*p+1]) - fmaxf(ml[2*p+1], ez[2*p+1]);
        float t0 = ex2f(-fabsf(y0));           // neg-abs folds into MUFU operand
        float t1 = ex2f(-fabsf(y1));
        ull tv = pk(t0, t1);
        ull rv = pk(fmaxf(y0, 0.f), fmaxf(y1, 0.f));
        ull q = ffma2(C.b6, tv, C.b5);
        q = ffma2(q, tv, C.b4);
        q = ffma2(q, tv, C.b3);
        q = ffma2(q, tv, C.b2);
        q = ffma2(q, tv, C.b1);                // R(t)
        ull v = ffma2(tv, q, rv);              // v = relu(y) + t*R(t) > 0
        prod = p ? fmul2(prod, v) : v;
    }
    float pa, pb; upk(prod, pa, pb);
    return lg2f(pa * pb);
}

// Padded mention smem: per mention 8 chunks x 20 floats (16 data + 4 pad);
// chunk stride 80B -> 8 c-addresses in disjoint bank groups.
#define MSTR 160

__global__ __launch_bounds__(256, 3) void ivr_kernel(const float* __restrict__ men,
                                                     const float* __restrict__ en,
                                                     float* __restrict__ out){
    __shared__ float s_men[32 * MSTR];
    __shared__ float s_gmp[256];
    __shared__ float s_gm[32];

    PolyC C;
    C.b6 = pk(-0.02512518f, -0.02512518f);
    C.b5 = pk( 0.1193046f,   0.1193046f);
    C.b4 = pk(-0.2746312f,  -0.2746312f);
    C.b3 = pk( 0.4555314f,   0.4555314f);
    C.b2 = pk(-0.7175598f,  -0.7175598f);
    C.b1 = pk( 1.4424753f,   1.4424753f);

    const int tid  = threadIdx.x;
    const int lane = tid & 31;
    const int wid  = tid >> 5;
    const int c    = lane & 7;
    const int nsub = lane >> 3;
    const int m0   = blockIdx.y * 32;

    for (int idx = tid; idx < 32 * 128; idx += 256){
        int m = idx >> 7, d = idx & 127;
        int cc = (d & 63) >> 3, k = d & 7, off = (d >= 64) ? 8 : 0;
        s_men[m * MSTR + cc * 20 + off + k] = men[(m0 + m) * 128 + d] * LOG2E;
    }
    __syncthreads();

    // per-mention self volume (identical value path -> approx error cancels)
    {
        int mi = tid >> 3, ci = tid & 7;
        const float* p = s_men + mi * MSTR + ci * 20;
        float ml[16];
#pragma unroll
        for (int k = 0; k < 16; ++k) ml[k] = p[k];
        s_gmp[tid] = chunk_lg2(ml, ml, ml + 8, C);
    }
    __syncthreads();
    if (tid < 32){
        float s = 0.f;
#pragma unroll
        for (int i = 0; i < 8; ++i) s += s_gmp[tid * 8 + i];
        s_gm[tid] = s;
    }
    __syncthreads();

    // entity chunk -> registers (prescaled). 20000 = 625*32, no guard.
    const int n = blockIdx.x * 32 + wid * 4 + nsub;
    float ez[8], eZ[8];
    {
        const float* erow = en + (size_t)n * 128;
        float4 a0 = *(const float4*)(erow + c * 8);
        float4 a1 = *(const float4*)(erow + c * 8 + 4);
        float4 b0 = *(const float4*)(erow + 64 + c * 8);
        float4 b1 = *(const float4*)(erow + 64 + c * 8 + 4);
        ez[0]=a0.x*LOG2E; ez[1]=a0.y*LOG2E; ez[2]=a0.z*LOG2E; ez[3]=a0.w*LOG2E;
        ez[4]=a1.x*LOG2E; ez[5]=a1.y*LOG2E; ez[6]=a1.z*LOG2E; ez[7]=a1.w*LOG2E;
        eZ[0]=b0.x*LOG2E; eZ[1]=b0.y*LOG2E; eZ[2]=b0.z*LOG2E; eZ[3]=b0.w*LOG2E;
        eZ[4]=b1.x*LOG2E; eZ[5]=b1.y*LOG2E; eZ[6]=b1.z*LOG2E; eZ[7]=b1.w*LOG2E;
    }

    const float* mbase = s_men + c * 20;

#pragma unroll 8
    for (int m = 0; m < 32; ++m){
        const float* p = mbase + m * MSTR;
        float ml[16];
        {
            float4 q0 = *(const float4*)(p);
            float4 q1 = *(const float4*)(p + 4);
            float4 q2 = *(const float4*)(p + 8);
            float4 q3 = *(const float4*)(p + 12);
            ml[0]=q0.x;  ml[1]=q0.y;  ml[2]=q0.z;  ml[3]=q0.w;
            ml[4]=q1.x;  ml[5]=q1.y;  ml[6]=q1.z;  ml[7]=q1.w;
            ml[8]=q2.x;  ml[9]=q2.y;  ml[10]=q2.z; ml[11]=q2.w;
            ml[12]=q3.x; ml[13]=q3.y; ml[14]=q3.z; ml[15]=q3.w;
        }
        float v = chunk_lg2(ml, ez, eZ, C);
        v += __shfl_xor_sync(0xFFFFFFFFu, v, 1);
        v += __shfl_xor_sync(0xFFFFFFFFu, v, 2);
        v += __shfl_xor_sync(0xFFFFFFFFu, v, 4);
        if (c == 0){
            out[(size_t)(m0 + m) * N_EN + n] = ex2f(v - s_gm[m]);
        }
    }
}

extern "C" void kernel_launch(void* const* d_in, const int* in_sizes, int n_in,
                              void* d_out, int out_size){
    const float* men = (const float*)d_in[0];
    const float* en  = (const float*)d_in[1];
    if (n_in >= 2 && in_sizes[0] > in_sizes[1]){
        const float* t = men; men = en; en = t;
    }
    float* out = (float*)d_out;

    dim3 grid(N_EN / 32, M_MEN / 32);   // 625 x 8
    ivr_kernel<<<grid, 256>>>(men, en, out);
}